// round 6
// baseline (speedup 1.0000x reference)
#include <cuda_runtime.h>
#include <float.h>

// ChessMoveSelector — algebraically collapsed.
// probs[b,n] = mask * softmax_n( moves[b,n,0]*w0 + moves[b,n,1]*w1 )
// where w = move_w^T @ comb_w[0, BD:].  All batch-constant terms (entire
// conv/fc board branch, biases) cancel inside the row softmax.
//
// Round 6 (= Round 5 resubmit after infra failure): 128-thread blocks
// (1024 CTAs -> balanced ~28 warps/SM single wave), integer redux.sync for
// BOTH max (order-preserving map) and exp-sum (2^24 fixed point; sum<=2^30,
// quantization error ~2e-6 rel), per-warp w hidden under the moves DRAM
// load, __expf.

#define NMAX 64
#define MD 128
#define BD 256

// Order-preserving float <-> int monotone mapping for integer max reduction.
__device__ __forceinline__ int f32_to_ordered_s32(float f) {
    int i = __float_as_int(f);
    return (i < 0) ? (i ^ 0x7fffffff) : i;   // now s32 compare == fp32 compare
}

__device__ __forceinline__ float warp_max_f32(float v) {
    int key = f32_to_ordered_s32(v);
    int r;
    asm volatile("redux.sync.max.s32 %0, %1, 0xffffffff;" : "=r"(r) : "r"(key));
    r = (r < 0) ? (r ^ 0x7fffffff) : r;      // invert mapping
    return __int_as_float(r);
}

__device__ __forceinline__ int warp_sum_s32(int v) {
    int r;
    asm volatile("redux.sync.add.s32 %0, %1, 0xffffffff;" : "=r"(r) : "r"(v));
    return r;
}

__global__ void __launch_bounds__(128, 8)
chess_move_softmax_kernel(
    const float4* __restrict__ moves4,  // [B*32] float4 == [B,64,2] floats
    const int*    __restrict__ lengths, // [B]
    const float2* __restrict__ move_w2, // [128] float2 == move_w[128,2]
    const float*  __restrict__ comb_w,  // [384]
    float2*       __restrict__ out2,    // [B*32] float2 == probs[B,64]
    int B)
{
    const int warp = (blockIdx.x * blockDim.x + threadIdx.x) >> 5;
    const int lane = threadIdx.x & 31;
    if (warp >= B) return;

    // ---- Issue ALL global loads up front so DRAM latencies overlap ----
    const int    len = lengths[warp];
    const float4 mv  = moves4[(size_t)warp * 32 + lane];   // 2 moves for this lane

    float cw[4];
    float2 mw[4];
    #pragma unroll
    for (int i = 0; i < 4; i++) {
        const int m = lane + i * 32;
        cw[i] = comb_w[BD + m];
        mw[i] = move_w2[m];
    }

    // ---- Per-warp collapsed weight vector w = move_w^T @ comb_w[BD:] ----
    // (entirely hidden under the in-flight moves DRAM load)
    float s0 = 0.f, s1 = 0.f;
    #pragma unroll
    for (int i = 0; i < 4; i++) {
        s0 = fmaf(cw[i], mw[i].x, s0);
        s1 = fmaf(cw[i], mw[i].y, s1);
    }
    #pragma unroll
    for (int off = 16; off > 0; off >>= 1) {
        s0 += __shfl_xor_sync(0xffffffffu, s0, off);
        s1 += __shfl_xor_sync(0xffffffffu, s1, off);
    }
    const float w0 = s0;
    const float w1 = s1;

    // ---- Scores for this lane's 2 moves ----
    const int  n0 = 2 * lane;
    const bool v0 = (n0     < len);
    const bool v1 = (n0 + 1 < len);

    const float sc0 = fmaf(mv.x, w0, mv.y * w1);
    const float sc1 = fmaf(mv.z, w0, mv.w * w1);

    // ---- Masked softmax over the 64 moves of this row ----
    const float mx = warp_max_f32(fmaxf(v0 ? sc0 : -FLT_MAX,
                                        v1 ? sc1 : -FLT_MAX));

    const float e0 = v0 ? __expf(sc0 - mx) : 0.f;   // in (0, 1]
    const float e1 = v1 ? __expf(sc1 - mx) : 0.f;

    // Fixed-point warp sum: e in [0,1], scale 2^24, sum <= 64*2^24 = 2^30.
    const int q = __float2int_rn(e0 * 16777216.0f)
                + __float2int_rn(e1 * 16777216.0f);
    const float sumf = (float)warp_sum_s32(q);      // = sum * 2^24 (quantized)
    const float inv  = __fdividef(16777216.0f, sumf);

    float2 r;
    r.x = e0 * inv;
    r.y = e1 * inv;
    out2[(size_t)warp * 32 + lane] = r;
}

extern "C" void kernel_launch(void* const* d_in, const int* in_sizes, int n_in,
                              void* d_out, int out_size)
{
    const float4* moves   = (const float4*)d_in[2];
    const int*    lengths = (const int*)d_in[3];
    const float2* move_w  = (const float2*)d_in[12];
    const float*  comb_w  = (const float*)d_in[14];
    float2* out = (float2*)d_out;

    const int B = in_sizes[3];                 // 4096 rows
    const int threads = 128;                   // 4 warps -> 4 rows per block
    const int warps_per_block = threads / 32;
    const int blocks = (B + warps_per_block - 1) / warps_per_block;  // 1024

    chess_move_softmax_kernel<<<blocks, threads>>>(moves, lengths, move_w, comb_w, out, B);
}

// round 8
// speedup vs baseline: 1.0729x; 1.0729x over previous
#include <cuda_runtime.h>
#include <float.h>

// ChessMoveSelector — algebraically collapsed.
// probs[b,n] = mask * softmax_n( moves[b,n,0]*w0 + moves[b,n,1]*w1 )
// where w = move_w^T @ comb_w[0, BD:].  All batch-constant terms (entire
// conv/fc board branch, biases) cancel inside the row softmax.
//
// Round 8 (= Round 7 resubmit after infra failure): round-4 launch shape
// (512thr x 256 CTAs — measured best; fewer, fatter CTAs win because the
// kernel is latency-bound, not balance-bound) + isolated tail optimization:
// integer redux.sync for max (order-preserving map) and exp-sum (2^24 fixed
// point), streaming cache hints on the once-touched streams.

#define NMAX 64
#define MD 128
#define BD 256

// Order-preserving float <-> int monotone mapping for integer max reduction.
__device__ __forceinline__ int f32_to_ordered_s32(float f) {
    int i = __float_as_int(f);
    return (i < 0) ? (i ^ 0x7fffffff) : i;   // now s32 compare == fp32 compare
}

__device__ __forceinline__ float warp_max_f32(float v) {
    int key = f32_to_ordered_s32(v);
    int r;
    asm volatile("redux.sync.max.s32 %0, %1, 0xffffffff;" : "=r"(r) : "r"(key));
    r = (r < 0) ? (r ^ 0x7fffffff) : r;      // invert mapping
    return __int_as_float(r);
}

__device__ __forceinline__ int warp_sum_s32(int v) {
    int r;
    asm volatile("redux.sync.add.s32 %0, %1, 0xffffffff;" : "=r"(r) : "r"(v));
    return r;
}

__global__ void __launch_bounds__(512)
chess_move_softmax_kernel(
    const float4* __restrict__ moves4,  // [B*32] float4 == [B,64,2] floats
    const int*    __restrict__ lengths, // [B]
    const float2* __restrict__ move_w2, // [128] float2 == move_w[128,2]
    const float*  __restrict__ comb_w,  // [384]
    float2*       __restrict__ out2,    // [B*32] float2 == probs[B,64]
    int B)
{
    const int warp = (blockIdx.x * blockDim.x + threadIdx.x) >> 5;
    const int lane = threadIdx.x & 31;
    if (warp >= B) return;

    // ---- Issue ALL global loads up front so DRAM latencies overlap ----
    const int    len = lengths[warp];
    const float4 mv  = __ldcs(&moves4[(size_t)warp * 32 + lane]);  // read-once: evict-first

    float cw[4];
    float2 mw[4];
    #pragma unroll
    for (int i = 0; i < 4; i++) {
        const int m = lane + i * 32;
        cw[i] = comb_w[BD + m];
        mw[i] = move_w2[m];
    }

    // ---- Per-warp collapsed weight vector w = move_w^T @ comb_w[BD:] ----
    // (hidden under the in-flight moves DRAM load)
    float s0 = 0.f, s1 = 0.f;
    #pragma unroll
    for (int i = 0; i < 4; i++) {
        s0 = fmaf(cw[i], mw[i].x, s0);
        s1 = fmaf(cw[i], mw[i].y, s1);
    }
    #pragma unroll
    for (int off = 16; off > 0; off >>= 1) {
        s0 += __shfl_xor_sync(0xffffffffu, s0, off);
        s1 += __shfl_xor_sync(0xffffffffu, s1, off);
    }
    const float w0 = s0;
    const float w1 = s1;

    // ---- Scores for this lane's 2 moves ----
    const int  n0 = 2 * lane;
    const bool v0 = (n0     < len);
    const bool v1 = (n0 + 1 < len);

    const float sc0 = fmaf(mv.x, w0, mv.y * w1);
    const float sc1 = fmaf(mv.z, w0, mv.w * w1);

    // ---- Masked softmax over the 64 moves of this row ----
    const float mx = warp_max_f32(fmaxf(v0 ? sc0 : -FLT_MAX,
                                        v1 ? sc1 : -FLT_MAX));

    const float e0 = v0 ? __expf(sc0 - mx) : 0.f;   // in (0, 1]
    const float e1 = v1 ? __expf(sc1 - mx) : 0.f;

    // Fixed-point warp sum: e in [0,1], scale 2^24, sum <= 64*2^24 = 2^30.
    const int q = __float2int_rn(e0 * 16777216.0f)
                + __float2int_rn(e1 * 16777216.0f);
    const float sumf = (float)warp_sum_s32(q);      // = sum * 2^24 (quantized)
    const float inv  = __fdividef(16777216.0f, sumf);

    float2 r;
    r.x = e0 * inv;
    r.y = e1 * inv;
    __stcs(&out2[(size_t)warp * 32 + lane], r);     // write-once: streaming store
}

extern "C" void kernel_launch(void* const* d_in, const int* in_sizes, int n_in,
                              void* d_out, int out_size)
{
    const float4* moves   = (const float4*)d_in[2];
    const int*    lengths = (const int*)d_in[3];
    const float2* move_w  = (const float2*)d_in[12];
    const float*  comb_w  = (const float*)d_in[14];
    float2* out = (float2*)d_out;

    const int B = in_sizes[3];                 // 4096 rows
    const int threads = 512;                   // 16 warps -> 16 rows per block
    const int warps_per_block = threads / 32;
    const int blocks = (B + warps_per_block - 1) / warps_per_block;  // 256

    chess_move_softmax_kernel<<<blocks, threads>>>(moves, lengths, move_w, comb_w, out, B);
}